// round 2
// baseline (speedup 1.0000x reference)
#include <cuda_runtime.h>
#include <cuda_bf16.h>
#include <cstdint>

#define Nn 10000
#define Ee 320000

typedef unsigned long long ull;

// Scratch (allocation-free rule: __device__ globals)
__device__ float g_aggH[Nn * 256];
__device__ float g_aggC[Nn * 3];
__device__ float g_cnt[Nn];

// ---------------------------------------------------------------------------
// helpers
// ---------------------------------------------------------------------------
__device__ __forceinline__ ull pack_dup(float a) {
    ull r;
    asm("mov.b64 %0,{%1,%1};" : "=l"(r) : "f"(a));
    return r;
}
__device__ __forceinline__ float2 unpack2(ull v) {
    float2 r;
    asm("mov.b64 {%0,%1},%2;" : "=f"(r.x), "=f"(r.y) : "l"(v));
    return r;
}
__device__ __forceinline__ void fma2(ull& d, ull a, ull b) {
    asm("fma.rn.f32x2 %0,%1,%2,%0;" : "+l"(d) : "l"(a), "l"(b));
}
__device__ __forceinline__ float silu(float x) {
    return x / (1.0f + __expf(-x));
}

// One K-chunk (32) of the register-blocked GEMM.
// A: row-major, stride AS floats, rows r0..r0+3 used by this thread.
// B: [32][256] smem chunk. Thread owns cols {4*tx+64*jj+q}.
template <int AS>
__device__ __forceinline__ void mma_chunk(const float* __restrict__ A,
                                          const float* __restrict__ B,
                                          ull acc[4][8], int tx, int r0) {
#pragma unroll 8
    for (int k = 0; k < 32; k++) {
        ull ap[4];
#pragma unroll
        for (int r = 0; r < 4; r++) {
            float a = A[(r0 + r) * AS + k];
            ap[r] = pack_dup(a);
        }
        const float* brow = B + k * 256 + 4 * tx;
#pragma unroll
        for (int jj = 0; jj < 4; jj++) {
            ulonglong2 bv = *reinterpret_cast<const ulonglong2*>(brow + 64 * jj);
#pragma unroll
            for (int r = 0; r < 4; r++) {
                fma2(acc[r][2 * jj + 0], ap[r], bv.x);
                fma2(acc[r][2 * jj + 1], ap[r], bv.y);
            }
        }
    }
}

// ---------------------------------------------------------------------------
// zero scratch
// ---------------------------------------------------------------------------
__global__ void zero_kernel() {
    int idx = blockIdx.x * 256 + threadIdx.x;
    int stride = gridDim.x * 256;
    for (int i = idx; i < Nn * 256; i += stride) g_aggH[i] = 0.0f;
    for (int i = idx; i < Nn * 3; i += stride) g_aggC[i] = 0.0f;
    for (int i = idx; i < Nn; i += stride) g_cnt[i] = 0.0f;
}

// ---------------------------------------------------------------------------
// fused edge kernel: edge MLP + coord MLP + segment-sum atomics
// ---------------------------------------------------------------------------
struct __align__(16) ESm {
    float X[64 * 260];   // activation ping-pong buffer
    float B[32 * 256];   // weight chunk
    union {
        float A[64 * 33];  // gathered A chunk (GEMM1 only)
        float P[64 * 17];  // partial dot buffer (phase D only)
    };
    float w512[256];     // We1 row 512 (radial weight)
    float wc2[256];      // Wc2
    int   rowI[64];
    int   colI[64];
    float rad[64];
    float cd[64 * 3];
};

__global__ __launch_bounds__(256, 2) void edge_kernel(
    const float* __restrict__ h, const float* __restrict__ coord,
    const int* __restrict__ ei,
    const float* __restrict__ We1, const float* __restrict__ be1,
    const float* __restrict__ We2, const float* __restrict__ be2,
    const float* __restrict__ Wc1, const float* __restrict__ bc1,
    const float* __restrict__ Wc2, const float* __restrict__ bc2) {
    extern __shared__ char smem_raw[];
    ESm& s = *reinterpret_cast<ESm*>(smem_raw);

    const int tid = threadIdx.x;
    const int tx = tid & 15;
    const int ty = tid >> 4;
    const int r0 = ty * 4;
    const int eb = blockIdx.x * 64;

    if (tid < 64) {
        int e = eb + tid;
        int ri = ei[e];
        int ci = ei[Ee + e];
        s.rowI[tid] = ri;
        s.colI[tid] = ci;
        float dx = coord[ri * 3 + 0] - coord[ci * 3 + 0];
        float dy = coord[ri * 3 + 1] - coord[ci * 3 + 1];
        float dz = coord[ri * 3 + 2] - coord[ci * 3 + 2];
        s.cd[tid * 3 + 0] = dx;
        s.cd[tid * 3 + 1] = dy;
        s.cd[tid * 3 + 2] = dz;
        s.rad[tid] = dx * dx + dy * dy + dz * dz;
    }
    s.w512[tid] = We1[512 * 256 + tid];
    s.wc2[tid] = Wc2[tid];
    __syncthreads();

    ull acc[4][8];
#pragma unroll
    for (int r = 0; r < 4; r++)
#pragma unroll
        for (int j = 0; j < 8; j++) acc[r][j] = 0ULL;

    const int rr = tid >> 2;           // row this thread stages (0..63)
    const int kk = (tid & 3) * 8;      // 8-float span within the 32-chunk

    // ---------------- GEMM1: [h_i | h_j] @ We1[0:512], K = 512 ----------------
    for (int kc = 0; kc < 16; kc++) {
        const int kb = kc * 32;
        // stage A chunk (gather from h, L2-resident)
        {
            const float* src = (kc < 8)
                ? h + (size_t)s.rowI[rr] * 256 + kb + kk
                : h + (size_t)s.colI[rr] * 256 + (kb - 256) + kk;
            float4 v0 = *reinterpret_cast<const float4*>(src);
            float4 v1 = *reinterpret_cast<const float4*>(src + 4);
            float* da = &s.A[rr * 33 + kk];
            da[0] = v0.x; da[1] = v0.y; da[2] = v0.z; da[3] = v0.w;
            da[4] = v1.x; da[5] = v1.y; da[6] = v1.z; da[7] = v1.w;
        }
        // stage B chunk (We1 rows kb..kb+31, flat 8192-float copy)
        {
            const float4* wsrc = reinterpret_cast<const float4*>(We1 + (size_t)kb * 256);
            float4* wdst = reinterpret_cast<float4*>(s.B);
#pragma unroll
            for (int i = 0; i < 8; i++) wdst[tid + 256 * i] = wsrc[tid + 256 * i];
        }
        __syncthreads();
        mma_chunk<33>(&s.A[0], s.B, acc, tx, r0);
        __syncthreads();
    }

    // epilogue 1: + radial*We1[512] + be1, silu -> X
    {
        float rads[4];
#pragma unroll
        for (int r = 0; r < 4; r++) rads[r] = s.rad[r0 + r];
#pragma unroll
        for (int r = 0; r < 4; r++) {
#pragma unroll
            for (int jj = 0; jj < 4; jj++) {
                int c0 = 4 * tx + 64 * jj;
                float2 p0 = unpack2(acc[r][2 * jj + 0]);
                float2 p1 = unpack2(acc[r][2 * jj + 1]);
                float4 o;
                o.x = silu(p0.x + rads[r] * s.w512[c0 + 0] + __ldg(&be1[c0 + 0]));
                o.y = silu(p0.y + rads[r] * s.w512[c0 + 1] + __ldg(&be1[c0 + 1]));
                o.z = silu(p1.x + rads[r] * s.w512[c0 + 2] + __ldg(&be1[c0 + 2]));
                o.w = silu(p1.y + rads[r] * s.w512[c0 + 3] + __ldg(&be1[c0 + 3]));
                *reinterpret_cast<float4*>(&s.X[(r0 + r) * 260 + c0]) = o;
                acc[r][2 * jj + 0] = 0ULL;
                acc[r][2 * jj + 1] = 0ULL;
            }
        }
    }
    __syncthreads();

    // ---------------- GEMM2: out1 @ We2, K = 256 ----------------
    for (int kc = 0; kc < 8; kc++) {
        const int kb = kc * 32;
        const float4* wsrc = reinterpret_cast<const float4*>(We2 + (size_t)kb * 256);
        float4* wdst = reinterpret_cast<float4*>(s.B);
#pragma unroll
        for (int i = 0; i < 8; i++) wdst[tid + 256 * i] = wsrc[tid + 256 * i];
        __syncthreads();
        mma_chunk<260>(&s.X[kb], s.B, acc, tx, r0);
        __syncthreads();
    }

    // epilogue 2: silu -> edge_feat; atomic agg_h; overwrite X
    {
        int nr[4];
#pragma unroll
        for (int r = 0; r < 4; r++) nr[r] = s.rowI[r0 + r];
#pragma unroll
        for (int r = 0; r < 4; r++) {
#pragma unroll
            for (int jj = 0; jj < 4; jj++) {
                int c0 = 4 * tx + 64 * jj;
                float2 p0 = unpack2(acc[r][2 * jj + 0]);
                float2 p1 = unpack2(acc[r][2 * jj + 1]);
                float4 o;
                o.x = silu(p0.x + __ldg(&be2[c0 + 0]));
                o.y = silu(p0.y + __ldg(&be2[c0 + 1]));
                o.z = silu(p1.x + __ldg(&be2[c0 + 2]));
                o.w = silu(p1.y + __ldg(&be2[c0 + 3]));
                float* gh = &g_aggH[(size_t)nr[r] * 256 + c0];
                atomicAdd(gh + 0, o.x);
                atomicAdd(gh + 1, o.y);
                atomicAdd(gh + 2, o.z);
                atomicAdd(gh + 3, o.w);
                *reinterpret_cast<float4*>(&s.X[(r0 + r) * 260 + c0]) = o;
                acc[r][2 * jj + 0] = 0ULL;
                acc[r][2 * jj + 1] = 0ULL;
            }
        }
    }
    __syncthreads();

    // ---------------- GEMM3: edge_feat @ Wc1, K = 256 ----------------
    for (int kc = 0; kc < 8; kc++) {
        const int kb = kc * 32;
        const float4* wsrc = reinterpret_cast<const float4*>(Wc1 + (size_t)kb * 256);
        float4* wdst = reinterpret_cast<float4*>(s.B);
#pragma unroll
        for (int i = 0; i < 8; i++) wdst[tid + 256 * i] = wsrc[tid + 256 * i];
        __syncthreads();
        mma_chunk<260>(&s.X[kb], s.B, acc, tx, r0);
        __syncthreads();
    }

    // epilogue 3: silu, partial dot with Wc2
    {
        float part[4] = {0.f, 0.f, 0.f, 0.f};
#pragma unroll
        for (int r = 0; r < 4; r++) {
#pragma unroll
            for (int jj = 0; jj < 4; jj++) {
                int c0 = 4 * tx + 64 * jj;
                float2 p0 = unpack2(acc[r][2 * jj + 0]);
                float2 p1 = unpack2(acc[r][2 * jj + 1]);
                float c_0 = silu(p0.x + __ldg(&bc1[c0 + 0]));
                float c_1 = silu(p0.y + __ldg(&bc1[c0 + 1]));
                float c_2 = silu(p1.x + __ldg(&bc1[c0 + 2]));
                float c_3 = silu(p1.y + __ldg(&bc1[c0 + 3]));
                part[r] += c_0 * s.wc2[c0 + 0] + c_1 * s.wc2[c0 + 1] +
                           c_2 * s.wc2[c0 + 2] + c_3 * s.wc2[c0 + 3];
            }
        }
        __syncthreads();  // X reads done; P (union w/ A) safe to write
#pragma unroll
        for (int r = 0; r < 4; r++) s.P[(r0 + r) * 17 + tx] = part[r];
    }
    __syncthreads();

    if (tid < 64) {
        float sum = 0.f;
#pragma unroll
        for (int t = 0; t < 16; t++) sum += s.P[tid * 17 + t];
        float scal = sum + __ldg(bc2);
        int ri = s.rowI[tid];
        atomicAdd(&g_aggC[ri * 3 + 0], s.cd[tid * 3 + 0] * scal);
        atomicAdd(&g_aggC[ri * 3 + 1], s.cd[tid * 3 + 1] * scal);
        atomicAdd(&g_aggC[ri * 3 + 2], s.cd[tid * 3 + 2] * scal);
        atomicAdd(&g_cnt[ri], 1.0f);
    }
}

// ---------------------------------------------------------------------------
// node kernel: node MLP + coord epilogue
// ---------------------------------------------------------------------------
struct __align__(16) NSm {
    float X[64 * 260];
    float B[32 * 256];
    float A[64 * 33];
};

__global__ __launch_bounds__(256, 2) void node_kernel(
    const float* __restrict__ h, const float* __restrict__ coord,
    const float* __restrict__ Wn1, const float* __restrict__ bn1,
    const float* __restrict__ Wn2, const float* __restrict__ bn2,
    float* __restrict__ out) {
    extern __shared__ char smem_raw[];
    NSm& s = *reinterpret_cast<NSm*>(smem_raw);

    const int tid = threadIdx.x;
    const int tx = tid & 15;
    const int ty = tid >> 4;
    const int r0 = ty * 4;
    const int nb = blockIdx.x * 64;

    ull acc[4][8];
#pragma unroll
    for (int r = 0; r < 4; r++)
#pragma unroll
        for (int j = 0; j < 8; j++) acc[r][j] = 0ULL;

    const int rr = tid >> 2;
    const int kk = (tid & 3) * 8;
    const int nrow = nb + rr;
    const bool vA = nrow < Nn;

    // GEMM-N1: [h | agg_h] @ Wn1, K = 512
    for (int kc = 0; kc < 16; kc++) {
        const int kb = kc * 32;
        float4 v0 = make_float4(0.f, 0.f, 0.f, 0.f);
        float4 v1 = v0;
        if (vA) {
            const float* src = (kc < 8)
                ? h + (size_t)nrow * 256 + kb + kk
                : g_aggH + (size_t)nrow * 256 + (kb - 256) + kk;
            v0 = *reinterpret_cast<const float4*>(src);
            v1 = *reinterpret_cast<const float4*>(src + 4);
        }
        float* da = &s.A[rr * 33 + kk];
        da[0] = v0.x; da[1] = v0.y; da[2] = v0.z; da[3] = v0.w;
        da[4] = v1.x; da[5] = v1.y; da[6] = v1.z; da[7] = v1.w;

        const float4* wsrc = reinterpret_cast<const float4*>(Wn1 + (size_t)kb * 256);
        float4* wdst = reinterpret_cast<float4*>(s.B);
#pragma unroll
        for (int i = 0; i < 8; i++) wdst[tid + 256 * i] = wsrc[tid + 256 * i];
        __syncthreads();
        mma_chunk<33>(&s.A[0], s.B, acc, tx, r0);
        __syncthreads();
    }

    // epilogue: silu -> X
#pragma unroll
    for (int r = 0; r < 4; r++) {
#pragma unroll
        for (int jj = 0; jj < 4; jj++) {
            int c0 = 4 * tx + 64 * jj;
            float2 p0 = unpack2(acc[r][2 * jj + 0]);
            float2 p1 = unpack2(acc[r][2 * jj + 1]);
            float4 o;
            o.x = silu(p0.x + __ldg(&bn1[c0 + 0]));
            o.y = silu(p0.y + __ldg(&bn1[c0 + 1]));
            o.z = silu(p1.x + __ldg(&bn1[c0 + 2]));
            o.w = silu(p1.y + __ldg(&bn1[c0 + 3]));
            *reinterpret_cast<float4*>(&s.X[(r0 + r) * 260 + c0]) = o;
            acc[r][2 * jj + 0] = 0ULL;
            acc[r][2 * jj + 1] = 0ULL;
        }
    }
    __syncthreads();

    // GEMM-N2: @ Wn2, K = 256
    for (int kc = 0; kc < 8; kc++) {
        const int kb = kc * 32;
        const float4* wsrc = reinterpret_cast<const float4*>(Wn2 + (size_t)kb * 256);
        float4* wdst = reinterpret_cast<float4*>(s.B);
#pragma unroll
        for (int i = 0; i < 8; i++) wdst[tid + 256 * i] = wsrc[tid + 256 * i];
        __syncthreads();
        mma_chunk<260>(&s.X[kb], s.B, acc, tx, r0);
        __syncthreads();
    }

    // epilogue: + bn2 -> h_out
#pragma unroll
    for (int r = 0; r < 4; r++) {
        int n = nb + r0 + r;
        if (n < Nn) {
#pragma unroll
            for (int jj = 0; jj < 4; jj++) {
                int c0 = 4 * tx + 64 * jj;
                float2 p0 = unpack2(acc[r][2 * jj + 0]);
                float2 p1 = unpack2(acc[r][2 * jj + 1]);
                float4 o;
                o.x = p0.x + __ldg(&bn2[c0 + 0]);
                o.y = p0.y + __ldg(&bn2[c0 + 1]);
                o.z = p1.x + __ldg(&bn2[c0 + 2]);
                o.w = p1.y + __ldg(&bn2[c0 + 3]);
                *reinterpret_cast<float4*>(&out[(size_t)n * 256 + c0]) = o;
            }
        }
    }

    // coord epilogue
    if (tid < 64) {
        int n = nb + tid;
        if (n < Nn) {
            float cnt = fmaxf(g_cnt[n], 1.0f);
            float inv = 1.0f / cnt;
#pragma unroll
            for (int d = 0; d < 3; d++) {
                out[(size_t)Nn * 256 + n * 3 + d] =
                    coord[n * 3 + d] + g_aggC[n * 3 + d] * inv;
            }
        }
    }
}

// ---------------------------------------------------------------------------
extern "C" void kernel_launch(void* const* d_in, const int* in_sizes, int n_in,
                              void* d_out, int out_size) {
    const float* h     = (const float*)d_in[0];
    const float* coord = (const float*)d_in[1];
    const int*   ei    = (const int*)d_in[2];
    const float* We1   = (const float*)d_in[3];
    const float* be1   = (const float*)d_in[4];
    const float* We2   = (const float*)d_in[5];
    const float* be2   = (const float*)d_in[6];
    const float* Wn1   = (const float*)d_in[7];
    const float* bn1   = (const float*)d_in[8];
    const float* Wn2   = (const float*)d_in[9];
    const float* bn2   = (const float*)d_in[10];
    const float* Wc1   = (const float*)d_in[11];
    const float* bc1   = (const float*)d_in[12];
    const float* Wc2   = (const float*)d_in[13];
    const float* bc2   = (const float*)d_in[14];
    float* out = (float*)d_out;

    cudaFuncSetAttribute(edge_kernel, cudaFuncAttributeMaxDynamicSharedMemorySize,
                         (int)sizeof(ESm));
    cudaFuncSetAttribute(node_kernel, cudaFuncAttributeMaxDynamicSharedMemorySize,
                         (int)sizeof(NSm));

    zero_kernel<<<1280, 256>>>();
    edge_kernel<<<Ee / 64, 256, sizeof(ESm)>>>(h, coord, ei, We1, be1, We2, be2,
                                               Wc1, bc1, Wc2, bc2);
    node_kernel<<<(Nn + 63) / 64, 256, sizeof(NSm)>>>(h, coord, Wn1, bn1, Wn2, bn2,
                                                      out);
}